// round 12
// baseline (speedup 1.0000x reference)
#include <cuda_runtime.h>
#include <cuda_bf16.h>

#define JNT 24
#define EPSF 1e-6f
#define SH_C0 0.28209479177387814f
#define SH_C1 0.4886025119029199f
#define C20 ( 1.0925484305920792f)
#define C21 (-1.0925484305920792f)
#define C22 ( 0.31539156525252005f)
#define C23 (-1.0925484305920792f)
#define C24 ( 0.5462742152960396f)

#define THREADS 128

typedef unsigned long long u64;

__device__ __forceinline__ float frcp(float x) {
    float r; asm("rcp.approx.ftz.f32 %0, %1;" : "=f"(r) : "f"(x)); return r;
}
__device__ __forceinline__ u64 pk2(float lo, float hi) {
    u64 r; asm("mov.b64 %0, {%1, %2};" : "=l"(r) : "f"(lo), "f"(hi)); return r;
}
__device__ __forceinline__ void upk2(float& lo, float& hi, u64 v) {
    asm("mov.b64 {%0, %1}, %2;" : "=f"(lo), "=f"(hi) : "l"(v));
}
__device__ __forceinline__ u64 ffma2(u64 a, u64 b, u64 c) {
    u64 d; asm("fma.rn.f32x2 %0, %1, %2, %3;" : "=l"(d) : "l"(a), "l"(b), "l"(c)); return d;
}

// Constant table: 6 float4 per joint (identical layout to R11)
//  q0 : (-r00, -r01, -r02, L0-t0)
//  q1 : (-r10, -r11, -r12, L1-t1)
//  q2 : (-r20, -r21, -r22, L2-t2)
//  q3 : (t0, t1, t2, base)        base = SH_C0*f0 + 0.5 - C22*f6
//  q4 : (f1', f2', f3', f4')      pre-scaled SH features
//  q5 : (f5', f6'', f7', f8')     f6'' = 3*C22*f6
__constant__ float4 cJ[JNT * 6];
__device__ float4 gPrep[JNT * 6];

__global__ void prep_kernel(const float* __restrict__ T,
                            const float* __restrict__ F,
                            const float* __restrict__ L)
{
    const int t = threadIdx.x;
    if (t >= JNT * 6) return;
    const int j = t / 6, k = t % 6;
    float4 q;
    if (k < 3) {
        const float* r = T + j * 16 + k * 4;   // r0 r1 r2 t
        q = make_float4(-r[0], -r[1], -r[2], L[j * 3 + k] - r[3]);
    } else if (k == 3) {
        const float base = fmaf(SH_C0, F[j * 9 + 0], 0.5f) - C22 * F[j * 9 + 6];
        q = make_float4(T[j * 16 + 3], T[j * 16 + 7], T[j * 16 + 11], base);
    } else if (k == 4) {
        q = make_float4(-SH_C1 * F[j * 9 + 1],
                         SH_C1 * F[j * 9 + 2],
                        -SH_C1 * F[j * 9 + 3],
                         C20   * F[j * 9 + 4]);
    } else {
        q = make_float4( C21        * F[j * 9 + 5],
                         3.f * C22  * F[j * 9 + 6],
                         C23        * F[j * 9 + 7],
                         C24        * F[j * 9 + 8]);
    }
    gPrep[t] = q;
}

__global__ __launch_bounds__(THREADS)
void shcaster_kernel(const float* __restrict__ xyz,
                     const float* __restrict__ vdir,
                     float* __restrict__ out,       // [2*N*3]
                     int N)
{
    const int gi = blockIdx.x * blockDim.x + threadIdx.x;   // pair index
    const int i0 = 2 * gi;
    if (i0 >= N) return;
    const bool hasB = (i0 + 1 < N);

    float xA0, xA1, xA2, vA0, vA1, vA2;
    float xB0 = 0.f, xB1 = 0.f, xB2 = 0.f, vB0 = 0.f, vB1 = 0.f, vB2 = 0.f;

    if (hasB) {
        const float2* xp = (const float2*)(xyz + 6 * (size_t)gi);
        const float2* vp = (const float2*)(vdir + 6 * (size_t)gi);
        const float2 a = xp[0], b = xp[1], c = xp[2];
        xA0 = a.x; xA1 = a.y; xA2 = b.x; xB0 = b.y; xB1 = c.x; xB2 = c.y;
        const float2 d = vp[0], e = vp[1], f = vp[2];
        vA0 = d.x; vA1 = d.y; vA2 = e.x; vB0 = e.y; vB1 = f.x; vB2 = f.y;
    } else {
        xA0 = xyz[3 * i0 + 0]; xA1 = xyz[3 * i0 + 1]; xA2 = xyz[3 * i0 + 2];
        vA0 = vdir[3 * i0 + 0]; vA1 = vdir[3 * i0 + 1]; vA2 = vdir[3 * i0 + 2];
    }

    float wsA = 0.f, wsB = 0.f;
    // Per point: 8 packed accumulators (junk lanes marked ~)
    u64 A0 = 0ull, A1 = 0ull, A2 = 0ull, A3 = 0ull;  // {m00,m01} {m02,~} {m10,m11} {m12,~}
    u64 A4 = 0ull, A5 = 0ull, A6 = 0ull, A7 = 0ull;  // {m20,m21} {m22,~} {ta0,ta1} {ta2,~}
    u64 B0 = 0ull, B1 = 0ull, B2 = 0ull, B3 = 0ull;
    u64 B4 = 0ull, B5 = 0ull, B6 = 0ull, B7 = 0ull;

#pragma unroll
    for (int j = 0; j < JNT; j++) {
        const float4 q0 = cJ[j * 6 + 0];
        const float4 q1 = cJ[j * 6 + 1];
        const float4 q2 = cJ[j * 6 + 2];
        const float4 q3 = cJ[j * 6 + 3];
        const float4 q4 = cJ[j * 6 + 4];
        const float4 q5 = cJ[j * 6 + 5];

        // natural pairs from the 128-bit constant loads
        const u64 p00 = pk2(q0.x, q0.y);
        const u64 p01 = pk2(q0.z, q0.w);
        const u64 p10 = pk2(q1.x, q1.y);
        const u64 p11 = pk2(q1.z, q1.w);
        const u64 p20 = pk2(q2.x, q2.y);
        const u64 p21 = pk2(q2.z, q2.w);
        const u64 p30 = pk2(q3.x, q3.y);
        const u64 p31 = pk2(q3.z, q3.w);

        // ---- point A: d = (L - t) - R x ----
        const float dA0 = fmaf(q0.x, xA0, fmaf(q0.y, xA1, fmaf(q0.z, xA2, q0.w)));
        const float dA1 = fmaf(q1.x, xA0, fmaf(q1.y, xA1, fmaf(q1.z, xA2, q1.w)));
        const float dA2 = fmaf(q2.x, xA0, fmaf(q2.y, xA1, fmaf(q2.z, xA2, q2.w)));
        // ---- point B ----
        const float dB0 = fmaf(q0.x, xB0, fmaf(q0.y, xB1, fmaf(q0.z, xB2, q0.w)));
        const float dB1 = fmaf(q1.x, xB0, fmaf(q1.y, xB1, fmaf(q1.z, xB2, q1.w)));
        const float dB2 = fmaf(q2.x, xB0, fmaf(q2.y, xB1, fmaf(q2.z, xB2, q2.w)));

        const float zzA = dA2 * dA2, zzB = dB2 * dB2;
        const float l2A = fmaf(dA0, dA0, fmaf(dA1, dA1, zzA));
        const float l2B = fmaf(dB0, dB0, fmaf(dB1, dB1, zzB));
        const float invA = rsqrtf(l2A), invB = rsqrtf(l2B);

        // SH dot, unnormalized d-space: rad = ((quad*inv + lin)*inv) + base
        const float linA = fmaf(q4.x, dA1, fmaf(q4.y, dA2, q4.z * dA0));
        const float linB = fmaf(q4.x, dB1, fmaf(q4.y, dB2, q4.z * dB0));
        const float xyA = dA0 * dA1, xyB = dB0 * dB1;
        const float yzA = dA1 * dA2, yzB = dB1 * dB2;
        const float xzA = dA0 * dA2, xzB = dB0 * dB2;
        const float pmA = fmaf(dA0, dA0, -(dA1 * dA1));
        const float pmB = fmaf(dB0, dB0, -(dB1 * dB1));
        const float quadA = fmaf(q4.w, xyA, fmaf(q5.x, yzA,
                            fmaf(q5.y, zzA, fmaf(q5.z, xzA, q5.w * pmA))));
        const float quadB = fmaf(q4.w, xyB, fmaf(q5.x, yzB,
                            fmaf(q5.y, zzB, fmaf(q5.z, xzB, q5.w * pmB))));
        const float radA = fmaf(fmaf(quadA, invA, linA), invA, q3.w);
        const float radB = fmaf(fmaf(quadB, invB, linB), invB, q3.w);

        const float rA = fmaxf(radA, EPSF), rB = fmaxf(radB, EPSF);
        const float lenA = l2A * invA, lenB = l2B * invB;
        const float wA = fmaxf(fmaf(-lenA, frcp(rA), 1.0f), 0.f);
        const float wB = fmaxf(fmaf(-lenB, frcp(rB), 1.0f), 0.f);

        wsA += wA;
        wsB += wB;
        const u64 wwA = pk2(wA, wA);
        const u64 wwB = pk2(wB, wB);
        A0 = ffma2(wwA, p00, A0); A1 = ffma2(wwA, p01, A1);
        A2 = ffma2(wwA, p10, A2); A3 = ffma2(wwA, p11, A3);
        A4 = ffma2(wwA, p20, A4); A5 = ffma2(wwA, p21, A5);
        A6 = ffma2(wwA, p30, A6); A7 = ffma2(wwA, p31, A7);
        B0 = ffma2(wwB, p00, B0); B1 = ffma2(wwB, p01, B1);
        B2 = ffma2(wwB, p10, B2); B3 = ffma2(wwB, p11, B3);
        B4 = ffma2(wwB, p20, B4); B5 = ffma2(wwB, p21, B5);
        B6 = ffma2(wwB, p30, B6); B7 = ffma2(wwB, p31, B7);
    }

    float* o1p = out + 6 * (size_t)gi;
    float* o2p = out + 3 * (size_t)N + 6 * (size_t)gi;

    // ---- epilogue A ----
    float m00, m01, m02, m10, m11, m12, m20, m21, m22, ta0, ta1, ta2, junk;
    upk2(m00, m01, A0); upk2(m02, junk, A1);
    upk2(m10, m11, A2); upk2(m12, junk, A3);
    upk2(m20, m21, A4); upk2(m22, junk, A5);
    upk2(ta0, ta1, A6); upk2(ta2, junk, A7);

    const float icA = frcp(fmaxf(wsA, EPSF));
    const bool valA = wsA > EPSF;
    const float mxA0 = fmaf(m00, xA0, fmaf(m01, xA1, m02 * xA2));
    const float mxA1 = fmaf(m10, xA0, fmaf(m11, xA1, m12 * xA2));
    const float mxA2 = fmaf(m20, xA0, fmaf(m21, xA1, m22 * xA2));
    const float oA0 = valA ? (ta0 - mxA0) * icA : xA0;
    const float oA1 = valA ? (ta1 - mxA1) * icA : xA1;
    const float oA2 = valA ? (ta2 - mxA2) * icA : xA2;
    const float nicA = -icA;
    const float gA0 = valA ? fmaf(m00, vA0, fmaf(m01, vA1, m02 * vA2)) * nicA : vA0;
    const float gA1 = valA ? fmaf(m10, vA0, fmaf(m11, vA1, m12 * vA2)) * nicA : vA1;
    const float gA2 = valA ? fmaf(m20, vA0, fmaf(m21, vA1, m22 * vA2)) * nicA : vA2;

    if (hasB) {
        // ---- epilogue B ----
        upk2(m00, m01, B0); upk2(m02, junk, B1);
        upk2(m10, m11, B2); upk2(m12, junk, B3);
        upk2(m20, m21, B4); upk2(m22, junk, B5);
        upk2(ta0, ta1, B6); upk2(ta2, junk, B7);

        const float icB = frcp(fmaxf(wsB, EPSF));
        const bool valB = wsB > EPSF;
        const float mxB0 = fmaf(m00, xB0, fmaf(m01, xB1, m02 * xB2));
        const float mxB1 = fmaf(m10, xB0, fmaf(m11, xB1, m12 * xB2));
        const float mxB2 = fmaf(m20, xB0, fmaf(m21, xB1, m22 * xB2));
        const float oB0 = valB ? (ta0 - mxB0) * icB : xB0;
        const float oB1 = valB ? (ta1 - mxB1) * icB : xB1;
        const float oB2 = valB ? (ta2 - mxB2) * icB : xB2;
        const float nicB = -icB;
        const float gB0 = valB ? fmaf(m00, vB0, fmaf(m01, vB1, m02 * vB2)) * nicB : vB0;
        const float gB1 = valB ? fmaf(m10, vB0, fmaf(m11, vB1, m12 * vB2)) * nicB : vB1;
        const float gB2 = valB ? fmaf(m20, vB0, fmaf(m21, vB1, m22 * vB2)) * nicB : vB2;

        float2* o1v = (float2*)o1p;
        float2* o2v = (float2*)o2p;
        o1v[0] = make_float2(oA0, oA1);
        o1v[1] = make_float2(oA2, oB0);
        o1v[2] = make_float2(oB1, oB2);
        o2v[0] = make_float2(gA0, gA1);
        o2v[1] = make_float2(gA2, gB0);
        o2v[2] = make_float2(gB1, gB2);
    } else {
        o1p[0] = oA0; o1p[1] = oA1; o1p[2] = oA2;
        o2p[0] = gA0; o2p[1] = gA1; o2p[2] = gA2;
    }
}

extern "C" void kernel_launch(void* const* d_in, const int* in_sizes, int n_in,
                              void* d_out, int out_size)
{
    const float* xyz  = (const float*)d_in[0];
    const float* vdir = (const float*)d_in[1];
    const float* T    = (const float*)d_in[2];
    const float* F    = (const float*)d_in[3];
    const float* L    = (const float*)d_in[4];
    float* out        = (float*)d_out;

    const int N = in_sizes[0] / 3;

    prep_kernel<<<1, JNT * 6>>>(T, F, L);

    void* prepPtr = nullptr;
    cudaGetSymbolAddress(&prepPtr, gPrep);
    cudaMemcpyToSymbolAsync(cJ, prepPtr, sizeof(float4) * JNT * 6, 0,
                            cudaMemcpyDeviceToDevice, 0);

    const int nPairs = (N + 1) / 2;
    const int blocks = (nPairs + THREADS - 1) / THREADS;
    shcaster_kernel<<<blocks, THREADS>>>(xyz, vdir, out, N);
}

// round 13
// speedup vs baseline: 1.3205x; 1.3205x over previous
#include <cuda_runtime.h>
#include <cuda_bf16.h>

#define JNT 24
#define EPSF 1e-6f
#define SH_C0 0.28209479177387814f
#define SH_C1 0.4886025119029199f
#define C20 ( 1.0925484305920792f)
#define C21 (-1.0925484305920792f)
#define C22 ( 0.31539156525252005f)
#define C23 (-1.0925484305920792f)
#define C24 ( 0.5462742152960396f)

#define THREADS 256

__device__ __forceinline__ float frcp(float x) {
    float r; asm("rcp.approx.ftz.f32 %0, %1;" : "=f"(r) : "f"(x)); return r;
}

// Constant table: 6 float4 per joint
//  q0 : (-r00, -r01, -r02, L0-t0)
//  q1 : (-r10, -r11, -r12, L1-t1)
//  q2 : (-r20, -r21, -r22, L2-t2)
//  q3 : (t0, t1, t2, base)        base = SH_C0*f0 + 0.5 - C22*f6
//  q4 : (f1', f2', f3', f4')      pre-scaled SH features
//  q5 : (f5', f6'', f7', f8')     f6'' = 3*C22*f6
__constant__ float4 cJ[JNT * 6];

// Prep kernel writes DIRECTLY into the device memory backing cJ (address
// obtained host-side via cudaGetSymbolAddress). The constant cache is
// invalidated at kernel-launch boundaries, so the main kernel sees the
// updated values. This removes the separate memcpy graph node.
__global__ void prep_kernel(float4* __restrict__ dst,
                            const float* __restrict__ T,
                            const float* __restrict__ F,
                            const float* __restrict__ L)
{
    const int t = threadIdx.x;
    if (t >= JNT * 6) return;
    const int j = t / 6, k = t % 6;
    float4 q;
    if (k < 3) {
        const float* r = T + j * 16 + k * 4;   // r0 r1 r2 t
        q = make_float4(-r[0], -r[1], -r[2], L[j * 3 + k] - r[3]);
    } else if (k == 3) {
        const float base = fmaf(SH_C0, F[j * 9 + 0], 0.5f) - C22 * F[j * 9 + 6];
        q = make_float4(T[j * 16 + 3], T[j * 16 + 7], T[j * 16 + 11], base);
    } else if (k == 4) {
        q = make_float4(-SH_C1 * F[j * 9 + 1],
                         SH_C1 * F[j * 9 + 2],
                        -SH_C1 * F[j * 9 + 3],
                         C20   * F[j * 9 + 4]);
    } else {
        q = make_float4( C21        * F[j * 9 + 5],
                         3.f * C22  * F[j * 9 + 6],
                         C23        * F[j * 9 + 7],
                         C24        * F[j * 9 + 8]);
    }
    dst[t] = q;
}

__global__ __launch_bounds__(THREADS)
void shcaster_kernel(const float* __restrict__ xyz,
                     const float* __restrict__ vdir,
                     float* __restrict__ out,       // [2*N*3]
                     int N)
{
    const int i = blockIdx.x * blockDim.x + threadIdx.x;
    if (i >= N) return;

    const float x0 = xyz[3 * i + 0];
    const float x1 = xyz[3 * i + 1];
    const float x2 = xyz[3 * i + 2];
    const float v0 = vdir[3 * i + 0];
    const float v1 = vdir[3 * i + 1];
    const float v2 = vdir[3 * i + 2];

    float wsum = 0.f;
    float ta0 = 0.f, ta1 = 0.f, ta2 = 0.f;            // sum w * t
    float m00 = 0.f, m01 = 0.f, m02 = 0.f;            // sum w * (-R)
    float m10 = 0.f, m11 = 0.f, m12 = 0.f;
    float m20 = 0.f, m21 = 0.f, m22 = 0.f;

#pragma unroll
    for (int j = 0; j < JNT; j++) {
        const float4 q0 = cJ[j * 6 + 0];
        const float4 q1 = cJ[j * 6 + 1];
        const float4 q2 = cJ[j * 6 + 2];
        const float4 q3 = cJ[j * 6 + 3];
        const float4 q4 = cJ[j * 6 + 4];
        const float4 q5 = cJ[j * 6 + 5];

        // d = (L - t) - R x  directly (negated R in table)
        const float d0 = fmaf(q0.x, x0, fmaf(q0.y, x1, fmaf(q0.z, x2, q0.w)));
        const float d1 = fmaf(q1.x, x0, fmaf(q1.y, x1, fmaf(q1.z, x2, q1.w)));
        const float d2 = fmaf(q2.x, x0, fmaf(q2.y, x1, fmaf(q2.z, x2, q2.w)));

        const float zz = d2 * d2;
        const float l2  = fmaf(d0, d0, fmaf(d1, d1, zz));
        const float inv = rsqrtf(l2);

        // SH dot in unnormalized d-space:
        // rad = ((quadD * inv + linD) * inv) + base
        const float linD = fmaf(q4.x, d1, fmaf(q4.y, d2, q4.z * d0));
        const float xy = d0 * d1;
        const float yz = d1 * d2;
        const float xz = d0 * d2;
        const float pm = fmaf(d0, d0, -(d1 * d1));   // x^2 - y^2
        const float quadD = fmaf(q4.w, xy,
                            fmaf(q5.x, yz,
                            fmaf(q5.y, zz,
                            fmaf(q5.z, xz, q5.w * pm))));
        const float tq  = fmaf(quadD, inv, linD);
        const float rad = fmaf(tq, inv, q3.w);

        // weight: r = max(relu(rad), EPS) = max(rad, EPS)
        const float r = fmaxf(rad, EPSF);
        const float len = l2 * inv;
        const float w = fmaxf(fmaf(-len, frcp(r), 1.0f), 0.f);

        wsum += w;
        ta0 = fmaf(w, q3.x, ta0);
        ta1 = fmaf(w, q3.y, ta1);
        ta2 = fmaf(w, q3.z, ta2);
        m00 = fmaf(w, q0.x, m00); m01 = fmaf(w, q0.y, m01); m02 = fmaf(w, q0.z, m02);
        m10 = fmaf(w, q1.x, m10); m11 = fmaf(w, q1.y, m11); m12 = fmaf(w, q1.z, m12);
        m20 = fmaf(w, q2.x, m20); m21 = fmaf(w, q2.y, m21); m22 = fmaf(w, q2.z, m22);
    }

    const float ic = frcp(fmaxf(wsum, EPSF));
    const bool valid = wsum > EPSF;

    // s = (sum w R) x + sum w t = tacc - (mneg x)
    const float mx0 = fmaf(m00, x0, fmaf(m01, x1, m02 * x2));
    const float mx1 = fmaf(m10, x0, fmaf(m11, x1, m12 * x2));
    const float mx2 = fmaf(m20, x0, fmaf(m21, x1, m22 * x2));
    const float o0 = valid ? (ta0 - mx0) * ic : x0;
    const float o1 = valid ? (ta1 - mx1) * ic : x1;
    const float o2 = valid ? (ta2 - mx2) * ic : x2;

    // vd_out = (mneg v) * (-ic)
    const float nic = -ic;
    const float e0 = fmaf(m00, v0, fmaf(m01, v1, m02 * v2)) * nic;
    const float e1 = fmaf(m10, v0, fmaf(m11, v1, m12 * v2)) * nic;
    const float e2 = fmaf(m20, v0, fmaf(m21, v1, m22 * v2)) * nic;
    const float g0 = valid ? e0 : v0;
    const float g1 = valid ? e1 : v1;
    const float g2 = valid ? e2 : v2;

    float* o1p = out + 3 * (size_t)i;
    float* o2p = out + 3 * ((size_t)N + i);
    o1p[0] = o0; o1p[1] = o1; o1p[2] = o2;
    o2p[0] = g0; o2p[1] = g1; o2p[2] = g2;
}

extern "C" void kernel_launch(void* const* d_in, const int* in_sizes, int n_in,
                              void* d_out, int out_size)
{
    const float* xyz  = (const float*)d_in[0];
    const float* vdir = (const float*)d_in[1];
    const float* T    = (const float*)d_in[2];
    const float* F    = (const float*)d_in[3];
    const float* L    = (const float*)d_in[4];
    float* out        = (float*)d_out;

    const int N = in_sizes[0] / 3;

    // Write the folded constants straight into cJ's backing memory.
    void* cjPtr = nullptr;
    cudaGetSymbolAddress(&cjPtr, cJ);
    prep_kernel<<<1, JNT * 6>>>((float4*)cjPtr, T, F, L);

    const int blocks = (N + THREADS - 1) / THREADS;
    shcaster_kernel<<<blocks, THREADS>>>(xyz, vdir, out, N);
}